// round 1
// baseline (speedup 1.0000x reference)
#include <cuda_runtime.h>
#include <math.h>
#include <stdint.h>

// Problem constants
// B=4, CIN=64, HID=64, H=W=64, K=3, N=9, D=256, INC=128, OUTC=256
// HP=WP=66, HW=4096, CN = INC*N = 1152

#define HW4 4096
#define CN 1152

// ---------------- scratch (device globals; no runtime allocation) ----------------
__device__ float d_tmp1[4 * 128 * 256];            // [b][c][d]   0.5 MB
__device__ float d_Amat[4 * CN * 256];             // [b][k=c*9+n][o]  4.7 MB (K-major)
__device__ float d_bm[4 * 256];                    // [b][o]
__device__ int   d_idx[4 * 9 * HW4 * 4];           // [b][n][hw][4] corner flat idx
__device__ float d_gw [4 * 9 * HW4 * 4];           // [b][n][hw][4] bilinear weights
__device__ float d_xpad[4 * 128 * 66 * 66];        // [b][c][66][66]  8.9 MB
__device__ float d_xoff[(size_t)4 * CN * HW4];     // [b][k=c*9+n][hw]  75.5 MB (K-major)
__device__ float d_comb[4 * 256 * HW4];            // [b][o][hw]  16.8 MB

// ---------------- 1. concat + ZeroPad2d(1) ----------------
__global__ void k_pad(const float* __restrict__ inp, const float* __restrict__ hcur) {
    int i = blockIdx.x * 256 + threadIdx.x;
    const int total = 4 * 128 * 66 * 66;
    if (i >= total) return;
    int wp = i % 66;
    int t = i / 66;
    int hp = t % 66; t /= 66;
    int c = t % 128; int b = t / 128;
    float v = 0.f;
    if (hp >= 1 && hp <= 64 && wp >= 1 && wp <= 64) {
        int sp = ((b * 64 + (c < 64 ? c : c - 64)) * 64 + (hp - 1)) * 64 + (wp - 1);
        v = (c < 64) ? inp[sp] : hcur[sp];
    }
    d_xpad[i] = v;
}

// ---------------- 2. hypernetwork stage 1: tmp1[b][c*256+d] = meta[b]·w1_w[row] + w1_b ----------------
// warp per row (32768 rows), 4 batches per warp
__global__ void k_w1(const float* __restrict__ meta, const float* __restrict__ w1w,
                     const float* __restrict__ w1b) {
    __shared__ float sm[1024];
    for (int i = threadIdx.x; i < 1024; i += 256) sm[i] = meta[i];
    __syncthreads();
    int gw = (blockIdx.x * 256 + threadIdx.x) >> 5;   // 0..32767
    int lane = threadIdx.x & 31;
    const float* row = w1w + (size_t)gw * 256;
    float a0 = 0.f, a1 = 0.f, a2 = 0.f, a3 = 0.f;
    #pragma unroll
    for (int k = lane; k < 256; k += 32) {
        float wv = row[k];
        a0 += wv * sm[k];
        a1 += wv * sm[256 + k];
        a2 += wv * sm[512 + k];
        a3 += wv * sm[768 + k];
    }
    #pragma unroll
    for (int s = 16; s > 0; s >>= 1) {
        a0 += __shfl_xor_sync(0xffffffffu, a0, s);
        a1 += __shfl_xor_sync(0xffffffffu, a1, s);
        a2 += __shfl_xor_sync(0xffffffffu, a2, s);
        a3 += __shfl_xor_sync(0xffffffffu, a3, s);
    }
    if (lane == 0) {
        float bb = w1b[gw];
        d_tmp1[gw]          = a0 + bb;
        d_tmp1[32768 + gw]  = a1 + bb;
        d_tmp1[65536 + gw]  = a2 + bb;
        d_tmp1[98304 + gw]  = a3 + bb;
    }
}

// ---------------- 3. per-gate bias: bm[b][o] = meta[b]·bl_w[o] + bl_b[o] ----------------
__global__ void k_bias(const float* __restrict__ meta, const float* __restrict__ blw,
                       const float* __restrict__ blb) {
    int gw = (blockIdx.x * 256 + threadIdx.x) >> 5;   // 0..1023
    int lane = threadIdx.x & 31;
    int b = gw >> 8, o = gw & 255;
    const float* row = blw + o * 256;
    const float* m = meta + b * 256;
    float a = 0.f;
    for (int k = lane; k < 256; k += 32) a += row[k] * m[k];
    #pragma unroll
    for (int s = 16; s > 0; s >>= 1) a += __shfl_xor_sync(0xffffffffu, a, s);
    if (lane == 0) d_bm[gw] = a + blb[o];
}

// ---------------- 4. hypernetwork stage 2: GEMM (512 x 2304 x 256) -> scatter into K-major A ----------------
// C[(b,c)][j] = tmp1[(b,c)]·w2_w[j] + w2_b[j];  A[b][c*9 + j%9][j/9] = C
__global__ __launch_bounds__(256) void k_hyper2(const float* __restrict__ w2w,
                                                const float* __restrict__ w2b) {
    __shared__ float As[16][132];
    __shared__ float Bs[16][132];
    int tid = threadIdx.x;
    int row0 = blockIdx.y * 128;     // rows = (b,c), 512 total
    int col0 = blockIdx.x * 128;     // j, 2304 total
    int ty = tid >> 4, tx = tid & 15;
    float acc[8][8] = {};
    for (int k0 = 0; k0 < 256; k0 += 16) {
        #pragma unroll
        for (int i = 0; i < 2; i++) {
            int l = tid + i * 256;
            int r = l >> 2;
            int kk4 = (l & 3) << 2;
            float4 va = *(const float4*)(d_tmp1 + (size_t)(row0 + r) * 256 + k0 + kk4);
            As[kk4 + 0][r] = va.x; As[kk4 + 1][r] = va.y;
            As[kk4 + 2][r] = va.z; As[kk4 + 3][r] = va.w;
            float4 vb = *(const float4*)(w2w + (size_t)(col0 + r) * 256 + k0 + kk4);
            Bs[kk4 + 0][r] = vb.x; Bs[kk4 + 1][r] = vb.y;
            Bs[kk4 + 2][r] = vb.z; Bs[kk4 + 3][r] = vb.w;
        }
        __syncthreads();
        #pragma unroll
        for (int kk = 0; kk < 16; kk++) {
            float ra[8], rb[8];
            #pragma unroll
            for (int i = 0; i < 8; i++) ra[i] = As[kk][ty * 8 + i];
            #pragma unroll
            for (int j = 0; j < 8; j++) rb[j] = Bs[kk][tx * 8 + j];
            #pragma unroll
            for (int i = 0; i < 8; i++)
                #pragma unroll
                for (int j = 0; j < 8; j++) acc[i][j] += ra[i] * rb[j];
        }
        __syncthreads();
    }
    #pragma unroll
    for (int i = 0; i < 8; i++) {
        int gr = row0 + ty * 8 + i;
        int b = gr >> 7, c = gr & 127;
        #pragma unroll
        for (int j = 0; j < 8; j++) {
            int jj = col0 + tx * 8 + j;
            int o = jj / 9, n = jj - o * 9;
            d_Amat[((size_t)b * CN + c * 9 + n) * 256 + o] = acc[i][j] + w2b[jj];
        }
    }
}

// ---------------- 5. offset conv (3x3) + sampling positions / bilinear weights ----------------
__global__ void k_offset(const float* __restrict__ mio, const float* __restrict__ pw,
                         const float* __restrict__ pb) {
    __shared__ float sw[162];
    __shared__ float sb[18];
    if (threadIdx.x < 162) sw[threadIdx.x] = pw[threadIdx.x];
    if (threadIdx.x < 18)  sb[threadIdx.x] = pb[threadIdx.x];
    __syncthreads();
    int b = blockIdx.y;
    int hw = blockIdx.x * 256 + threadIdx.x;
    int h = hw >> 6, w = hw & 63;
    const float* plane = mio + b * 4096;
    float v[9];
    #pragma unroll
    for (int kh = 0; kh < 3; kh++)
        #pragma unroll
        for (int kw = 0; kw < 3; kw++) {
            int hi = h - 1 + kh, wi = w - 1 + kw;
            v[kh * 3 + kw] = (hi >= 0 && hi < 64 && wi >= 0 && wi < 64) ? plane[hi * 64 + wi] : 0.f;
        }
    #pragma unroll
    for (int n = 0; n < 9; n++) {
        float offx = sb[n], offy = sb[9 + n];
        #pragma unroll
        for (int t = 0; t < 9; t++) {
            offx += v[t] * sw[n * 9 + t];
            offy += v[t] * sw[(9 + n) * 9 + t];
        }
        float px = (float)(h + 1) + (float)(n / 3 - 1) + offx;
        float py = (float)(w + 1) + (float)(n % 3 - 1) + offy;
        float fx = floorf(px), fy = floorf(py);
        int xlt = min(max((int)fx, 0), 65);
        int xrb = min(max((int)fx + 1, 0), 65);
        int ylt = min(max((int)fy, 0), 65);
        int yrb = min(max((int)fy + 1, 0), 65);
        float pcx = fminf(fmaxf(px, 0.f), 65.f);
        float pcy = fminf(fmaxf(py, 0.f), 65.f);
        float glt = (1.f + ((float)xlt - pcx)) * (1.f + ((float)ylt - pcy));
        float grb = (1.f - ((float)xrb - pcx)) * (1.f - ((float)yrb - pcy));
        float glb = (1.f + ((float)xlt - pcx)) * (1.f - ((float)yrb - pcy));
        float grt = (1.f - ((float)xrb - pcx)) * (1.f + ((float)ylt - pcy));
        int base = ((b * 9 + n) * HW4 + hw) * 4;
        *(int4*)(d_idx + base) = make_int4(xlt * 66 + ylt, xrb * 66 + yrb,
                                           xlt * 66 + yrb, xrb * 66 + ylt);
        *(float4*)(d_gw + base) = make_float4(glt, grb, glb, grt);
    }
}

// ---------------- 6. bilinear gather -> x_off in K-major [b][c*9+n][hw] ----------------
__global__ __launch_bounds__(256) void k_sample() {
    int b = blockIdx.z, n = blockIdx.y;
    int hw = blockIdx.x * 256 + threadIdx.x;
    int base = ((b * 9 + n) * HW4 + hw) * 4;
    int4 id = *(const int4*)(d_idx + base);
    float4 g = *(const float4*)(d_gw + base);
    const float* xp = d_xpad + (size_t)b * 128 * 4356;
    float* op = d_xoff + ((size_t)b * CN + n) * HW4 + hw;
    #pragma unroll 4
    for (int c = 0; c < 128; c++) {
        const float* pl = xp + c * 4356;
        float val = g.x * pl[id.x] + g.y * pl[id.y] + g.z * pl[id.z] + g.w * pl[id.w];
        op[(size_t)c * (9 * HW4)] = val;
    }
}

// ---------------- 7. main contraction: per-b C[256][4096] = A^T(256x1152) * B(1152x4096) + bias ----------------
__global__ __launch_bounds__(256) void k_gemm() {
    int b = blockIdx.z;
    const float* Ag = d_Amat + (size_t)b * CN * 256;
    const float* Bg = d_xoff + (size_t)b * CN * HW4;
    float* Cg = d_comb + (size_t)b * 256 * HW4;
    int row0 = blockIdx.y * 128, col0 = blockIdx.x * 128;
    __shared__ float As[16][128];
    __shared__ float Bs[16][128];
    int tid = threadIdx.x, ty = tid >> 4, tx = tid & 15;
    float acc[8][8] = {};
    for (int k0 = 0; k0 < CN; k0 += 16) {
        #pragma unroll
        for (int i = 0; i < 2; i++) {
            int l = tid + i * 256;
            int kk = l >> 5;
            int m4 = (l & 31) << 2;
            *(float4*)&As[kk][m4] = *(const float4*)(Ag + (size_t)(k0 + kk) * 256 + row0 + m4);
            *(float4*)&Bs[kk][m4] = *(const float4*)(Bg + (size_t)(k0 + kk) * HW4 + col0 + m4);
        }
        __syncthreads();
        #pragma unroll
        for (int kk = 0; kk < 16; kk++) {
            float ra[8], rb[8];
            *(float4*)(ra)     = *(const float4*)&As[kk][ty * 8];
            *(float4*)(ra + 4) = *(const float4*)&As[kk][ty * 8 + 4];
            *(float4*)(rb)     = *(const float4*)&Bs[kk][tx * 8];
            *(float4*)(rb + 4) = *(const float4*)&Bs[kk][tx * 8 + 4];
            #pragma unroll
            for (int i = 0; i < 8; i++)
                #pragma unroll
                for (int j = 0; j < 8; j++) acc[i][j] += ra[i] * rb[j];
        }
        __syncthreads();
    }
    #pragma unroll
    for (int i = 0; i < 8; i++) {
        int r = row0 + ty * 8 + i;
        float bias = d_bm[b * 256 + r];
        float4 o0 = make_float4(acc[i][0] + bias, acc[i][1] + bias,
                                acc[i][2] + bias, acc[i][3] + bias);
        float4 o1 = make_float4(acc[i][4] + bias, acc[i][5] + bias,
                                acc[i][6] + bias, acc[i][7] + bias);
        *(float4*)(Cg + (size_t)r * HW4 + col0 + tx * 8)     = o0;
        *(float4*)(Cg + (size_t)r * HW4 + col0 + tx * 8 + 4) = o1;
    }
}

// ---------------- 8. LSTM gates -> (h_next, c_next) ----------------
__global__ void k_gates(const float* __restrict__ ccur, float* __restrict__ out) {
    int i = blockIdx.x * 256 + threadIdx.x;     // < 1048576
    int b = i >> 18;
    int r = i & 262143;
    int hid = r >> 12, hw = r & 4095;
    const float* cb = d_comb + (size_t)b * 256 * HW4;
    float ci = cb[(size_t)(hid)       * HW4 + hw];
    float cf = cb[(size_t)(hid + 64)  * HW4 + hw];
    float co = cb[(size_t)(hid + 128) * HW4 + hw];
    float cg = cb[(size_t)(hid + 192) * HW4 + hw];
    float ig = 1.f / (1.f + expf(-ci));
    float fg = 1.f / (1.f + expf(-cf));
    float og = 1.f / (1.f + expf(-co));
    float gg = tanhf(cg);
    float cn = fg * ccur[i] + ig * gg;
    float hn = og * tanhf(cn);
    out[i] = hn;
    out[1048576 + i] = cn;
}

// ---------------- launch ----------------
extern "C" void kernel_launch(void* const* d_in, const int* in_sizes, int n_in,
                              void* d_out, int out_size) {
    const float* inp  = (const float*)d_in[0];
    const float* hcur = (const float*)d_in[1];
    const float* ccur = (const float*)d_in[2];
    const float* meta = (const float*)d_in[3];
    const float* mio  = (const float*)d_in[4];
    const float* w1w  = (const float*)d_in[5];
    const float* w1b  = (const float*)d_in[6];
    const float* w2w  = (const float*)d_in[7];
    const float* w2b  = (const float*)d_in[8];
    const float* blw  = (const float*)d_in[9];
    const float* blb  = (const float*)d_in[10];
    const float* pw   = (const float*)d_in[11];
    const float* pb   = (const float*)d_in[12];
    float* out = (float*)d_out;

    k_pad   <<<8712, 256>>>(inp, hcur);
    k_w1    <<<4096, 256>>>(meta, w1w, w1b);
    k_bias  <<<128, 256>>>(meta, blw, blb);
    k_hyper2<<<dim3(18, 4), 256>>>(w2w, w2b);
    k_offset<<<dim3(16, 4), 256>>>(mio, pw, pb);
    k_sample<<<dim3(16, 9, 4), 256>>>();
    k_gemm  <<<dim3(32, 2, 4), 256>>>();
    k_gates <<<4096, 256>>>(ccur, out);
}